// round 16
// baseline (speedup 1.0000x reference)
#include <cuda_runtime.h>

#define NS 64
#define NB 8192
#define HP 128
#define HH 64
#define NR 11
#define RC 231
#define GAPN 10
#define MCN 10000
#define DT (1.0f/64.0f)
#define NHB 50

__device__ int   g_histp[NHB*NR*20];
__device__ __align__(16) float g_A[NS*RC*HH];
__device__ __align__(16) float g_B[NS*RC];
__device__ __align__(16) float g_W3[NS*NR*6*HH];
__device__ __align__(16) float g_b3[NS*NR*6];
__device__ float4 g_P1[NS*6*32];
__device__ float4 g_P2[NS*HH*32];
__device__ float4 g_Pb[NS*32];
__device__ float4 g_Pb2[NS*32];
__device__ __align__(16) float g_in6[NS*6*NB];
__device__ __align__(16) float g_a6[NS*6*NB];
__device__ __align__(16) float g_wt[NS*NB];
__device__ __align__(16) int   g_idx[NS*NB];
__device__ __align__(16) float g_d[NS*NB];

__global__ void __launch_bounds__(256) kh(const float* __restrict__ mc,
                                          const float* __restrict__ jm){
  __shared__ int sh[NR*20];
  int tid=threadIdx.x;
  if(tid<NR*20) sh[tid]=0;
  __syncthreads();
  const int chunk=(MCN*NR+NHB-1)/NHB;
  int lo=blockIdx.x*chunk, hi=min(lo+chunk,MCN*NR);
  for(int i=lo+tid;i<hi;i+=256){
    int r=i%NR; float u=mc[i]; const float* row=jm+r*20; int c=0;
    #pragma unroll
    for(int j=0;j<20;j++) c += (u<row[j]) ? 1 : 0;
    atomicAdd(&sh[r*20+(20-c)],1);
  }
  __syncthreads();
  if(tid<NR*20) g_histp[blockIdx.x*NR*20+tid]=sh[tid];
}

__global__ void __launch_bounds__(256) kA2B(const float* __restrict__ Wf3,
                                            const float* __restrict__ bf3,
                                            const float* __restrict__ jl,
                                            const float* __restrict__ jr,
                                            const float* __restrict__ cr){
  int t=blockIdx.x, chunk=blockIdx.y;
  __shared__ float sW[HP*65];
  __shared__ float swt[4][HP];
  __shared__ float sb[HP];
  __shared__ float s_jl[20*HP];
  __shared__ float s_jr[NR*HP];
  __shared__ float s_mc[NR*HP];
  __shared__ int   s_hist[NR*20];
  __shared__ float s_cr[NR];
  int tid=threadIdx.x;
  for(int idx=tid; idx<HH*HP; idx+=256){
    int h=idx>>7, p=idx&127;
    sW[p*65+h]=Wf3[t*HH*HP+idx];
  }
  if(tid<HP) sb[tid]=bf3[t*HP+tid];
  for(int i=tid;i<20*HP;i+=256) s_jl[i]=jl[i];
  for(int i=tid;i<NR*HP;i+=256) s_jr[i]=jr[i];
  if(tid<NR) s_cr[tid]=cr[tid];
  if(tid<NR*20){
    int a=0;
    #pragma unroll 10
    for(int b=0;b<NHB;b++) a+=g_histp[b*NR*20+tid];
    s_hist[tid]=a;
  }
  __syncthreads();
  for(int i=tid;i<NR*HP;i+=256){
    int r=i>>7, p=i&127;
    float acc=0.f;
    #pragma unroll
    for(int k=0;k<GAPN;k++){
      acc += (float)s_hist[r*20+k]      * s_jl[k*HP+p];
      acc += (float)s_hist[r*20+10+k]   * s_jl[(GAPN+k)*HP+p];
    }
    s_mc[i]=s_cr[r]*(acc*(1.0f/MCN));
  }
  __syncthreads();
  int h=tid&63, g=tid>>6;
  int rcEnd=min(chunk*29+29,RC);
  for(int rc0=chunk*29; rc0<rcEnd; rc0+=4){
    __syncthreads();
    for(int idx=tid; idx<4*HP; idx+=256){
      int gg=idx>>7, p=idx&127; int rc=rc0+gg;
      float w=0.f;
      if(rc<RC){
        int r=rc/21, c=rc-r*21, d=c-10;
        float j=0.f;
        if(d>0) j=s_jl[(d-1)*HP+p]; else if(d<0) j=s_jl[(GAPN+(-d-1))*HP+p];
        w=s_jr[r*HP+p]*(j - s_mc[r*HP+p]*DT);
      }
      swt[gg][p]=w;
    }
    __syncthreads();
    int rc=rc0+g;
    if(rc<rcEnd){
      float a=0.f;
      #pragma unroll 8
      for(int p=0;p<HP;p++) a += sW[p*65+h]*swt[g][p];
      g_A[(t*RC+rc)*HH+h]=a;
    }
    if(tid<4 && rc0+tid<rcEnd){
      float b0=0.f,b1=0.f;
      #pragma unroll 8
      for(int p=0;p<HP;p+=2){ b0+=sb[p]*swt[tid][p]; b1+=sb[p+1]*swt[tid][p+1]; }
      g_B[t*RC+rc0+tid]=b0+b1;
    }
  }
}

__global__ void __launch_bounds__(384) kEP(const float* __restrict__ W3,
                                           const float* __restrict__ emb,
                                           const float* __restrict__ b3,
  const float* __restrict__ W1, const float* __restrict__ b1,
  const float* __restrict__ W2, const float* __restrict__ b2,
  const float* __restrict__ Wf1, const float* __restrict__ bf1,
  const float* __restrict__ Wf2, const float* __restrict__ bf2){
  int t=blockIdx.x, tid=threadIdx.x;
  __shared__ float se[NR*HP];
  for(int i=tid;i<NR*HP;i+=384) se[i]=emb[t*NR*HP+i];
  __syncthreads();
  int h=tid/6, o=tid-h*6;
  float acc[NR];
  #pragma unroll
  for(int r=0;r<NR;r++) acc[r]=0.f;
  const float* W=W3+t*HH*768+h*768+o;
  for(int p=0;p<HP;p++){
    float wv=W[p*6];
    #pragma unroll
    for(int r=0;r<NR;r++) acc[r] += se[r*HP+p]*wv;
  }
  #pragma unroll
  for(int r=0;r<NR;r++) g_W3[((t*NR+r)*6+o)*HH+h]=acc[r];
  if(tid<6){
    float a2[NR];
    #pragma unroll
    for(int r=0;r<NR;r++) a2[r]=0.f;
    const float* bb=b3+t*768+tid;
    for(int p=0;p<HP;p++){
      float bv=bb[p*6];
      #pragma unroll
      for(int r=0;r<NR;r++) a2[r] += se[r*HP+p]*bv;
    }
    #pragma unroll
    for(int r=0;r<NR;r++) g_b3[(t*NR+r)*6+tid]=a2[r];
  }
  for(int idx=tid; idx<HH*32; idx+=384){
    int i=idx>>5, l=idx&31; int b=t*HH*HH+i*HH+2*l;
    g_P2[(t*HH+i)*32+l]=make_float4(W2[b],W2[b+1],Wf2[b],Wf2[b+1]);
  }
  for(int idx=tid; idx<6*32; idx+=384){
    int i=idx>>5, l=idx&31; int b=t*6*HH+i*HH+2*l;
    g_P1[(t*6+i)*32+l]=make_float4(W1[b],W1[b+1],Wf1[b],Wf1[b+1]);
  }
  if(tid<32){
    int b=t*HH+2*tid;
    g_Pb [t*32+tid]=make_float4(b1[b],b1[b+1],bf1[b],bf1[b+1]);
    g_Pb2[t*32+tid]=make_float4(b2[b],b2[b+1],bf2[b],bf2[b+1]);
  }
}

__device__ __forceinline__ float tanh_(float x){
  float e=__expf(2.f*x); return 1.f-__fdividef(2.f,e+1.f);
}

struct TS {
  float xt[3], xi[3], yi[3];
  float gx[9], gy[9];
  float fun; int rt, act;
};
struct NZ { float jv,sv,db0,db1,dy0,dy1,dy2; };

__device__ __forceinline__ NZ ldnz(int t,int p,
  const float* __restrict__ juf,const float* __restrict__ suf,
  const float* __restrict__ dBx,const float* __restrict__ dBy){
  NZ n;
  n.jv=juf[t*NB+p]; n.sv=suf[t*NB+p];
  float2 db=*(const float2*)(dBx+(size_t)(t*NB+p)*2);
  n.db0=db.x; n.db1=db.y;
  const float* dyp=dBy+(size_t)(t*NB+p)*3;
  n.dy0=dyp[0]; n.dy1=dyp[1]; n.dy2=dyp[2];
  return n;
}

// branchless reflect: identical arithmetic, select-gated commits
__device__ __forceinline__ void reflS(float* p, float* m){
  float nr=sqrtf(p[0]*p[0]+p[1]*p[1]+p[2]*p[2]);
  float d=fmaxf(nr,1e-12f);
  float n0=p[0]/d, n1=p[1]/d, n2=p[2]/d;
  bool o=nr>5.0f;
  float s=10.0f-nr;
  float q0=n0*m[0]+n1*m[3]+n2*m[6];
  float q1=n0*m[1]+n1*m[4]+n2*m[7];
  float q2=n0*m[2]+n1*m[5]+n2*m[8];
  p[0]=o?n0*s:p[0]; p[1]=o?n1*s:p[1]; p[2]=o?n2*s:p[2];
  m[0]=o?m[0]-2.f*n0*q0:m[0]; m[1]=o?m[1]-2.f*n0*q1:m[1]; m[2]=o?m[2]-2.f*n0*q2:m[2];
  m[3]=o?m[3]-2.f*n1*q0:m[3]; m[4]=o?m[4]-2.f*n1*q1:m[4]; m[5]=o?m[5]-2.f*n1*q2:m[5];
  m[6]=o?m[6]-2.f*n2*q0:m[6]; m[7]=o?m[7]-2.f*n2*q1:m[7]; m[8]=o?m[8]-2.f*n2*q2:m[8];
}

__device__ __forceinline__ void stepT(TS& S, int t, int p, const NZ& n,
  const float* s_jm, const float* s_cr, const float* s_cfr, const float* s_inv){
  // store MLP inputs (pre-update state)
  g_in6[(t*6+0)*NB+p]=S.xi[0]; g_in6[(t*6+1)*NB+p]=S.xi[1]; g_in6[(t*6+2)*NB+p]=S.xi[2];
  g_in6[(t*6+3)*NB+p]=S.yi[0]; g_in6[(t*6+4)*NB+p]=S.yi[1]; g_in6[(t*6+5)*NB+p]=S.yi[2];

  int ridx=min(max(S.rt-10,0),10);
  const float* row=s_jm+ridx*20;
  int c=0;
  #pragma unroll
  for(int j=0;j<20;j++) c += (n.sv<row[j]) ? 1 : 0;
  int ind=20-c;
  int sz=(ind<10)?(ind+1):(-(ind-9));
  int drt=(n.jv<s_cr[ridx]*DT)?sz:0;

  float dot=S.xt[0]*S.xt[0]+S.xt[1]*S.xt[1]+S.xt[2]*S.xt[2];
  float aa=fminf(fmaxf(S.xt[2]*rsqrtf(fmaxf(dot,1e-24f)),-1.f),1.f);
  float st=-aa, ct=sqrtf(fmaxf(1.f-aa*aa,0.f));
  float dxy=S.xt[0]*S.xt[0]+S.xt[1]*S.xt[1];
  float inv=rsqrtf(fmaxf(dxy,1e-30f));
  bool ok=dxy>0.f;
  float cp=ok?S.xt[0]*inv:1.f, sp=ok?S.xt[1]*inv:0.f;
  float T0=cp*ct, T1=-sp, T2=cp*st;
  float T3=sp*ct, T4=cp,  T5=sp*st;
  float T6=-st,   T8=ct;
  float sdx=s_inv[S.rt-10];

  float m0=sdx*(n.db1*T1-n.db0*T2);
  float m1=sdx*(n.db1*T4-n.db0*T5);
  float m2=sdx*(n.db1*(0.f)-n.db0*T8) + sdx*n.db1*0.f; // placeholder not used
  m2=sdx*(n.db1*0.f-n.db0*T8); // T7==0
  float a0=S.gx[0]*m0+S.gx[1]*m1+S.gx[2]*m2;
  float a1=S.gx[3]*m0+S.gx[4]*m1+S.gx[5]*m2;
  float a2=S.gx[6]*m0+S.gx[7]*m1+S.gx[8]*m2;
  float a3=S.gy[0]*n.dy0+S.gy[1]*n.dy1+S.gy[2]*n.dy2;
  float a4=S.gy[3]*n.dy0+S.gy[4]*n.dy1+S.gy[5]*n.dy2;
  float a5=S.gy[6]*n.dy0+S.gy[7]*n.dy1+S.gy[8]*n.dy2;
  int cc=drt+10;
  g_a6[(t*6+0)*NB+p]=a0; g_a6[(t*6+1)*NB+p]=a1; g_a6[(t*6+2)*NB+p]=a2;
  g_a6[(t*6+3)*NB+p]=a3; g_a6[(t*6+4)*NB+p]=a4; g_a6[(t*6+5)*NB+p]=a5;
  g_wt[t*NB+p]=S.act ? __expf(-S.fun) : 0.f;
  g_idx[t*NB+p]=(ridx<<8)|cc;

  float fm=S.act?1.f:0.f;
  S.fun += fm*(s_cfr[ridx]*DT);
  float dX0=sdx*n.db0, dX1=sdx*n.db1;
  float x2=dX0*dX0;
  float s_t = 1.f - x2*(0.5f - x2*(0.0416666667f - x2*0.00138888889f));
  float c_t = -dX0*(1.f - x2*(0.166666667f - x2*(0.00833333333f - x2*1.98412698e-4f)));
  float y2=dX1*dX1;
  float c_p = 1.f - y2*(0.5f - y2*(0.0416666667f - y2*0.00138888889f));
  float s_p = dX1*(1.f - y2*(0.166666667f - y2*(0.00833333333f - y2*1.98412698e-4f)));
  float cx=s_t*c_p-1.f, cy=s_t*s_p, cz=c_t;
  float d0=T0*cx+T1*cy+T2*cz;
  float d1=T3*cx+T4*cy+T5*cz;
  float d2=T6*cx+0.f*cy+T8*cz;
  S.xt[0]+=fm*d0; S.xt[1]+=fm*d1; S.xt[2]+=fm*d2;
  S.xi[0]+=fm*(S.gx[0]*d0+S.gx[1]*d1+S.gx[2]*d2);
  S.xi[1]+=fm*(S.gx[3]*d0+S.gx[4]*d1+S.gx[5]*d2);
  S.xi[2]+=fm*(S.gx[6]*d0+S.gx[7]*d1+S.gx[8]*d2);
  S.yi[0]+=fm*a3; S.yi[1]+=fm*a4; S.yi[2]+=fm*a5;
  int nrt=min(max(S.rt+drt,10),20);
  S.rt=S.act?nrt:S.rt;
  reflS(S.xi,S.gx); reflS(S.yi,S.gy);
  float e0=S.xi[0]-S.yi[0], e1=S.xi[1]-S.yi[1], e2=S.xi[2]-S.yi[2];
  if(sqrtf(e0*e0+e1*e1+e2*e2)<0.1f) S.act=0;
}

// ---- Phase 1: two interleaved independent chains per thread ----
__global__ void __launch_bounds__(64) ktraj(
  const int* __restrict__ rt0, const float* __restrict__ xt0,
  const float* __restrict__ yt0, const float* __restrict__ dBx,
  const float* __restrict__ dBy, const float* __restrict__ juf,
  const float* __restrict__ suf, const float* __restrict__ jm,
  const float* __restrict__ cr, const float* __restrict__ cfr,
  float* __restrict__ out)
{
  int tid=threadIdx.x;
  __shared__ float s_jm[NR*20];
  __shared__ float s_cr[NR], s_cfr[NR], s_inv[NR];
  for(int i=tid;i<NR*20;i+=64) s_jm[i]=jm[i];
  if(tid<NR){
    s_cr[tid]=cr[tid]; s_cfr[tid]=cfr[tid];
    s_inv[tid]=1.0f/(float)(tid+10);
  }
  __syncthreads();
  int p0=blockIdx.x*64+tid;
  int p1=p0+4096;

  TS A, B;
  A.rt=rt0[p0]; B.rt=rt0[p1];
  #pragma unroll
  for(int k=0;k<3;k++){
    A.xt[k]=xt0[p0*3+k]; A.xi[k]=A.xt[k]; A.yi[k]=yt0[p0*3+k];
    B.xt[k]=xt0[p1*3+k]; B.xi[k]=B.xt[k]; B.yi[k]=yt0[p1*3+k];
  }
  #pragma unroll
  for(int k=0;k<9;k++){
    float id=(k==0||k==4||k==8)?1.f:0.f;
    A.gx[k]=id; A.gy[k]=id; B.gx[k]=id; B.gy[k]=id;
  }
  A.fun=0.f; B.fun=0.f; A.act=1; B.act=1;

  NZ nA=ldnz(0,p0,juf,suf,dBx,dBy);
  NZ nB=ldnz(0,p1,juf,suf,dBx,dBy);
  for(int t=0;t<NS;t++){
    NZ mA,mB;
    if(t+1<NS){
      mA=ldnz(t+1,p0,juf,suf,dBx,dBy);
      mB=ldnz(t+1,p1,juf,suf,dBx,dBy);
    }
    stepT(A,t,p0,nA,s_jm,s_cr,s_cfr,s_inv);
    stepT(B,t,p1,nB,s_jm,s_cr,s_cfr,s_inv);
    nA=mA; nB=mB;
  }
  {
    float e0=A.xi[0]-A.yi[0], e1=A.xi[1]-A.yi[1], e2=A.xi[2]-A.yi[2];
    out[NB+p0]=A.act ? __expf(-(e0*e0+e1*e1+e2*e2))*__expf(-A.fun) : 0.f;
    e0=B.xi[0]-B.yi[0]; e1=B.xi[1]-B.yi[1]; e2=B.xi[2]-B.yi[2];
    out[NB+p1]=B.act ? __expf(-(e0*e0+e1*e1+e2*e2))*__expf(-B.fun) : 0.f;
  }
}

// ---- Phase 2: 4 rows per warp; c0 computed here (moved out of ktraj) ----
__global__ void __launch_bounds__(128) kmlp(){
  int tid=threadIdx.x, l=tid&31, wl=tid>>5;
  __shared__ __align__(16) float2 sh[4][4][HH];
  int gw=blockIdx.x*4+wl;
  int row=4*gw;
  int t=row>>13, p=row&(NB-1);

  float4 bb=g_Pb[t*32+l];
  float4 acc[4];
  #pragma unroll
  for(int r=0;r<4;r++) acc[r]=bb;
  {
    const float4* Wp=g_P1+t*6*32;
    #pragma unroll
    for(int i=0;i<6;i++){
      float4 wv=Wp[i*32+l];
      #pragma unroll
      for(int r=0;r<4;r++){
        float x=g_in6[(t*6+i)*NB+p+r];
        acc[r].x+=x*wv.x; acc[r].y+=x*wv.y;
        acc[r].z+=x*wv.z; acc[r].w+=x*wv.w;
      }
    }
  }
  #pragma unroll
  for(int r=0;r<4;r++){
    ((float4*)sh[wl][r])[l]=make_float4(tanh_(acc[r].x),tanh_(acc[r].z),
                                        tanh_(acc[r].y),tanh_(acc[r].w));
  }
  __syncwarp();
  float4 b2v=g_Pb2[t*32+l];
  #pragma unroll
  for(int r=0;r<4;r++) acc[r]=b2v;
  {
    const float4* Wp=g_P2+t*HH*32;
    #pragma unroll 8
    for(int i=0;i<HH;i++){
      float4 wv=Wp[i*32+l];
      #pragma unroll
      for(int r=0;r<4;r++){
        float2 x=sh[wl][r][i];
        acc[r].x+=x.x*wv.x; acc[r].y+=x.x*wv.y;
        acc[r].z+=x.y*wv.z; acc[r].w+=x.y*wv.w;
      }
    }
  }
  float s[4], c0v[4];
  #pragma unroll
  for(int r=0;r<4;r++){
    float2 h2=make_float2(tanh_(acc[r].x),tanh_(acc[r].y));
    float2 f2=make_float2(tanh_(acc[r].z),tanh_(acc[r].w));
    int idx=g_idx[t*NB+p+r];
    int ridx=idx>>8, rc=ridx*21+(idx&255);
    const float* Wp=g_W3+(t*NR+ridx)*6*HH;
    const float* bp=g_b3+(t*NR+ridx)*6;
    float a6r[6];
    #pragma unroll
    for(int o=0;o<6;o++) a6r[o]=g_a6[(t*6+o)*NB+p+r];
    float sv=0.f;
    #pragma unroll
    for(int o=0;o<6;o++){
      float2 wa=*(const float2*)(Wp+o*HH+2*l);
      sv += a6r[o]*(h2.x*wa.x+h2.y*wa.y);
    }
    float2 aa2=*(const float2*)(g_A+(t*RC+rc)*HH+2*l);
    sv += f2.x*aa2.x+f2.y*aa2.y;
    s[r]=sv;
    float c0=a6r[0]*bp[0];
    #pragma unroll
    for(int o=1;o<6;o++) c0 += a6r[o]*bp[o];
    c0 += g_B[t*RC+rc];
    c0v[r]=c0;
  }
  #pragma unroll
  for(int k=16;k;k>>=1){
    #pragma unroll
    for(int r=0;r<4;r++) s[r]+=__shfl_xor_sync(0xffffffffu,s[r],k);
  }
  if(l==0){
    float4 wt=*(const float4*)(g_wt+t*NB+p);
    float4 dd;
    dd.x=wt.x*(s[0]+c0v[0]); dd.y=wt.y*(s[1]+c0v[1]);
    dd.z=wt.z*(s[2]+c0v[2]); dd.w=wt.w*(s[3]+c0v[3]);
    *(float4*)(g_d+t*NB+p)=dd;
  }
}

__global__ void __launch_bounds__(256) kfin(const float* __restrict__ u,
                                            float* __restrict__ out){
  int p=blockIdx.x*256+threadIdx.x;
  float acc=u[0];
  #pragma unroll 8
  for(int t=0;t<NS;t++) acc+=g_d[t*NB+p];
  out[p]=acc;
}

extern "C" void kernel_launch(void* const* d_in, const int* in_sizes, int n_in,
                              void* d_out, int out_size) {
  const float* u   =(const float*)d_in[0];
  const float* jr  =(const float*)d_in[1];
  const float* jl  =(const float*)d_in[2];
  const float* W1  =(const float*)d_in[3];
  const float* b1  =(const float*)d_in[4];
  const float* W2  =(const float*)d_in[5];
  const float* b2  =(const float*)d_in[6];
  const float* W3  =(const float*)d_in[7];
  const float* b3  =(const float*)d_in[8];
  const float* emb =(const float*)d_in[9];
  const float* Wf1 =(const float*)d_in[10];
  const float* bf1 =(const float*)d_in[11];
  const float* Wf2 =(const float*)d_in[12];
  const float* bf2 =(const float*)d_in[13];
  const float* Wf3 =(const float*)d_in[14];
  const float* bf3 =(const float*)d_in[15];
  const int*   rt0 =(const int*)  d_in[16];
  const float* xt0 =(const float*)d_in[17];
  const float* yt0 =(const float*)d_in[18];
  const float* dBx =(const float*)d_in[19];
  const float* dBy =(const float*)d_in[20];
  const float* juf =(const float*)d_in[21];
  const float* suf =(const float*)d_in[22];
  const float* mcu =(const float*)d_in[23];
  const float* jm  =(const float*)d_in[24];
  const float* cr  =(const float*)d_in[25];
  const float* cfr =(const float*)d_in[26];

  kh<<<NHB,256>>>(mcu,jm);
  kA2B<<<dim3(NS,8),256>>>(Wf3,bf3,jl,jr,cr);
  kEP<<<NS,384>>>(W3,emb,b3,W1,b1,W2,b2,Wf1,bf1,Wf2,bf2);
  ktraj<<<64,64>>>(rt0,xt0,yt0,dBx,dBy,juf,suf,jm,cr,cfr,(float*)d_out);
  kmlp<<<NS*NB/16,128>>>();
  kfin<<<NB/256,256>>>(u,(float*)d_out);
}